// round 10
// baseline (speedup 1.0000x reference)
#include <cuda_runtime.h>
#include <cuda_bf16.h>
#include <math.h>

#define N_NODES 100000
#define M_PAD   100096              // 782 * 128
#define D_IN    128
#define D_HID   256
#define D_OUT   64
#define N_EDGES 1600000
#define SCAN_NB ((N_NODES + 1023) / 1024)   // 98

typedef unsigned int       u32;
typedef unsigned long long u64;
typedef __nv_bfloat16      bf16;
typedef __nv_bfloat162     bf162;

// ---------------- scratch (static device globals; no allocation) ----------------
__device__ int   g_is64;
__device__ int   g_cnt[N_NODES];
__device__ int   g_cur[N_NODES];
__device__ int   g_off[N_NODES + 1];
__device__ int   g_bsum[128];
__device__ int   g_csr[N_EDGES];
__device__ float g_agg1[(size_t)M_PAD * D_IN];   // padded rows stay 0 (static init)
__device__ float g_h[(size_t)M_PAD * D_HID];
__device__ float g_z[(size_t)M_PAD * D_OUT];

// ---------------- helpers ----------------
__device__ __forceinline__ u32 smem_u32(const void* p) {
    u32 a;
    asm("{ .reg .u64 t; cvta.to.shared.u64 t, %1; cvt.u32.u64 %0, t; }" : "=r"(a) : "l"(p));
    return a;
}
__device__ __forceinline__ void split2(float v, bf16& h, bf16& l) {
    h = __float2bfloat16_rn(v);
    l = __float2bfloat16_rn(v - __bfloat162float(h));
}
__device__ __forceinline__ void ldsm4(u32* r, u32 addr) {
    asm volatile("ldmatrix.sync.aligned.m8n8.x4.shared.b16 {%0,%1,%2,%3}, [%4];"
        : "=r"(r[0]), "=r"(r[1]), "=r"(r[2]), "=r"(r[3]) : "r"(addr));
}
__device__ __forceinline__ void mma16816(float* c, const u32* a, u32 b0, u32 b1) {
    asm volatile(
        "mma.sync.aligned.m16n8k16.row.col.f32.bf16.bf16.f32 "
        "{%0,%1,%2,%3}, {%4,%5,%6,%7}, {%8,%9}, {%0,%1,%2,%3};"
        : "+f"(c[0]), "+f"(c[1]), "+f"(c[2]), "+f"(c[3])
        : "r"(a[0]), "r"(a[1]), "r"(a[2]), "r"(a[3]), "r"(b0), "r"(b1));
}

// edge index accessors (dtype decided at runtime)
__device__ __forceinline__ int edge_src(const void* ei, int i, int is64) {
    return is64 ? (int)((const long long*)ei)[i] : ((const int*)ei)[i];
}
__device__ __forceinline__ int edge_dst(const void* ei, int i, int is64) {
    return is64 ? (int)((const long long*)ei)[N_EDGES + i] : ((const int*)ei)[N_EDGES + i];
}

__global__ void k_detect(const int* __restrict__ ei_words) {
    int all_zero = 1;
    for (int i = 0; i < 64; i++)
        if (ei_words[2 * i + 1] != 0) { all_zero = 0; break; }
    g_is64 = all_zero;
}

// ---------------- CSR build ----------------
__global__ void k_zero() {
    int i = blockIdx.x * blockDim.x + threadIdx.x;
    if (i < N_NODES) { g_cnt[i] = 0; g_cur[i] = 0; }
}

__global__ void k_hist(const void* __restrict__ ei) {
    int is64 = g_is64;
    int i = blockIdx.x * blockDim.x + threadIdx.x;
    if (i < N_EDGES) {
        int d = edge_dst(ei, i, is64);
        if (d >= 0 && d < N_NODES) atomicAdd(&g_cnt[d], 1);
    }
}

__device__ __forceinline__ int warp_incl_scan(int x, int lane) {
#pragma unroll
    for (int o = 1; o < 32; o <<= 1) {
        int t = __shfl_up_sync(0xffffffffu, x, o);
        if (lane >= o) x += t;
    }
    return x;
}

__global__ void k_scan1() {
    int b = blockIdx.x, tid = threadIdx.x;
    int i = b * 1024 + tid;
    int v = (i < N_NODES) ? g_cnt[i] : 0;
    int lane = tid & 31, w = tid >> 5;
    int x = warp_incl_scan(v, lane);
    __shared__ int ws[32];
    if (lane == 31) ws[w] = x;
    __syncthreads();
    if (w == 0) {
        int t = ws[lane];
        t = warp_incl_scan(t, lane);
        ws[lane] = t;
    }
    __syncthreads();
    int incl = x + (w ? ws[w - 1] : 0);
    if (i < N_NODES) g_off[i] = incl - v;
    if (tid == 1023) g_bsum[b] = incl;
}

__global__ void k_scan2() {
    int tid = threadIdx.x, lane = tid & 31, w = tid >> 5;
    int v = (tid < SCAN_NB) ? g_bsum[tid] : 0;
    int x = warp_incl_scan(v, lane);
    __shared__ int ws[4];
    if (lane == 31) ws[w] = x;
    __syncthreads();
    int add = 0;
#pragma unroll
    for (int i = 0; i < 4; i++) if (i < w) add += ws[i];
    int incl = x + add;
    if (tid < SCAN_NB) g_bsum[tid] = incl - v;
}

__global__ void k_scan3() {
    int i = blockIdx.x * blockDim.x + threadIdx.x;
    if (i < N_NODES) g_off[i] += g_bsum[i >> 10];
    if (i == 0) g_off[N_NODES] = N_EDGES;
}

__global__ void k_fill(const void* __restrict__ ei) {
    int is64 = g_is64;
    int i = blockIdx.x * blockDim.x + threadIdx.x;
    if (i < N_EDGES) {
        int d = edge_dst(ei, i, is64);
        int s = edge_src(ei, i, is64);
        if (d >= 0 && d < N_NODES && s >= 0 && s < N_NODES) {
            int p = atomicAdd(&g_cur[d], 1);
            g_csr[g_off[d] + p] = s;
        }
    }
}

// ---------------- aggregation 1 (proven, fp32 out) ----------------
__global__ void k_agg1(const float* __restrict__ x) {
    int warp = (blockIdx.x * blockDim.x + threadIdx.x) >> 5;
    if (warp >= N_NODES) return;
    int lane = threadIdx.x & 31;
    int s0 = g_off[warp], s1 = g_off[warp + 1];
    float4 acc = make_float4(0.f, 0.f, 0.f, 0.f);
    for (int e = s0; e < s1; e++) {
        int s = g_csr[e];
        float4 v = *(const float4*)(x + (size_t)s * D_IN + lane * 4);
        acc.x += v.x; acc.y += v.y; acc.z += v.z; acc.w += v.w;
    }
    float sc = 1.f / (float)max(s1 - s0, 1);
    acc.x *= sc; acc.y *= sc; acc.z *= sc; acc.w *= sc;
    *(float4*)(g_agg1 + (size_t)warp * D_IN + lane * 4) = acc;
}

// ================= bf16 3-split tensor-core GEMM (in-kernel split) =================
// C[M_PAD, LDC] = A[M_PAD, KTOT] @ B[*, KTOT]^T (+bias, relu).
// fp32 in/out; hi/lo bf16 split done during staging. Tiles BM=128 BN=64 BK=32.
// 256 threads = 8 warps (4 m x 2 n). Single-buffered static smem (30.7 KB).
// NOTE: B tiles are stored n-major/k-contiguous, which IS the native col-major
// k x n fragment layout -> B fragments use NON-trans ldmatrix (fix vs round 7).
#define AST 40     // bf16 elems per A/B smem row (80 B, 16B-aligned rows)

template <int KTOT, int LDC, bool RELU, bool HASBIAS>
__device__ __forceinline__ void hmma_body(const float* __restrict__ A,
                                          const float* __restrict__ B,
                                          const float* __restrict__ bias,
                                          float* __restrict__ C) {
    __shared__ __align__(16) bf16 sAh[128 * AST];
    __shared__ __align__(16) bf16 sAl[128 * AST];
    __shared__ __align__(16) bf16 sBh[64 * AST];
    __shared__ __align__(16) bf16 sBl[64 * AST];

    const int tid  = threadIdx.x;
    const int wid  = tid >> 5;
    const int lane = tid & 31;
    const int g    = lane >> 2;
    const int tig  = lane & 3;
    const int m0   = blockIdx.x * 128;
    const int n0   = blockIdx.y * 64;
    const int wm   = (wid & 3) * 32;
    const int wn   = (wid >> 2) * 32;

    const u32 uAh = smem_u32(sAh), uAl = smem_u32(sAl);
    const u32 uBh = smem_u32(sBh), uBl = smem_u32(sBl);
    // per-lane ldmatrix addressing: row offset lane&15, col offset (lane>>4)*8
    const int lr = lane & 15;
    const int lc = (lane >> 4) << 3;

    float acc[2][4][4];
#pragma unroll
    for (int i = 0; i < 2; i++)
#pragma unroll
        for (int j = 0; j < 4; j++)
#pragma unroll
            for (int c = 0; c < 4; c++) acc[i][j][c] = 0.f;

    for (int kt = 0; kt < KTOT / 32; kt++) {
        const int k0 = kt * 32;
        __syncthreads();   // previous compute done before overwriting tiles
        // ---- stage A: 128 x 32 fp32 -> split -> sAh/sAl ----
#pragma unroll
        for (int i = 0; i < 4; i++) {
            int e = tid + i * 256;              // 0..1023
            int row = e >> 3, c4 = (e & 7) * 4;
            float4 v = *(const float4*)(A + (size_t)(m0 + row) * KTOT + k0 + c4);
            bf16 h0, l0, h1, l1, h2, l2, h3, l3;
            split2(v.x, h0, l0); split2(v.y, h1, l1);
            split2(v.z, h2, l2); split2(v.w, h3, l3);
            int o = row * AST + c4;
            *(bf162*)(sAh + o)     = bf162(h0, h1);
            *(bf162*)(sAh + o + 2) = bf162(h2, h3);
            *(bf162*)(sAl + o)     = bf162(l0, l1);
            *(bf162*)(sAl + o + 2) = bf162(l2, l3);
        }
        // ---- stage B: 64 x 32 fp32 -> split -> sBh/sBl ----
#pragma unroll
        for (int i = 0; i < 2; i++) {
            int e = tid + i * 256;              // 0..511
            int row = e >> 3, c4 = (e & 7) * 4;
            float4 v = *(const float4*)(B + (size_t)(n0 + row) * KTOT + k0 + c4);
            bf16 h0, l0, h1, l1, h2, l2, h3, l3;
            split2(v.x, h0, l0); split2(v.y, h1, l1);
            split2(v.z, h2, l2); split2(v.w, h3, l3);
            int o = row * AST + c4;
            *(bf162*)(sBh + o)     = bf162(h0, h1);
            *(bf162*)(sBh + o + 2) = bf162(h2, h3);
            *(bf162*)(sBl + o)     = bf162(l0, l1);
            *(bf162*)(sBl + o + 2) = bf162(l2, l3);
        }
        __syncthreads();

        // ---- compute: 2 k-slabs of 16, three compensation segments ----
#pragma unroll
        for (int ks = 0; ks < 2; ks++) {
            const int kc = ks * 16 + lc;
            u32 ah[2][4], al[2][4], bh[2][4], bl[2][4];
#pragma unroll
            for (int ma = 0; ma < 2; ma++) {
                u32 off = (u32)((wm + ma * 16 + lr) * AST + kc) * 2;
                ldsm4(ah[ma], uAh + off);
                ldsm4(al[ma], uAl + off);
            }
#pragma unroll
            for (int p = 0; p < 2; p++) {
                u32 off = (u32)((wn + p * 16 + lr) * AST + kc) * 2;
                ldsm4(bh[p], uBh + off);   // FIX: non-trans (k-contiguous rows
                ldsm4(bl[p], uBl + off);   // are already the col-major fragment)
            }
#pragma unroll
            for (int ma = 0; ma < 2; ma++)
#pragma unroll
                for (int nb = 0; nb < 4; nb++) {
                    int p = nb >> 1, j = nb & 1;
                    mma16816(acc[ma][nb], ah[ma], bh[p][j], bh[p][j + 2]);
                    mma16816(acc[ma][nb], al[ma], bh[p][j], bh[p][j + 2]);
                    mma16816(acc[ma][nb], ah[ma], bl[p][j], bl[p][j + 2]);
                }
        }
    }

    // ---- epilogue ----
#pragma unroll
    for (int ma = 0; ma < 2; ma++)
#pragma unroll
        for (int nb = 0; nb < 4; nb++) {
            int row = m0 + wm + ma * 16 + g;
            int col = n0 + wn + nb * 8 + 2 * tig;
            float c0 = acc[ma][nb][0], c1 = acc[ma][nb][1];
            float c2 = acc[ma][nb][2], c3 = acc[ma][nb][3];
            if (HASBIAS) {
                float bv0 = __ldg(bias + col), bv1 = __ldg(bias + col + 1);
                c0 += bv0; c1 += bv1; c2 += bv0; c3 += bv1;
            }
            if (RELU) {
                c0 = fmaxf(c0, 0.f); c1 = fmaxf(c1, 0.f);
                c2 = fmaxf(c2, 0.f); c3 = fmaxf(c3, 0.f);
            }
            *(float2*)(C + (size_t)row * LDC + col)       = make_float2(c0, c1);
            *(float2*)(C + (size_t)(row + 8) * LDC + col) = make_float2(c2, c3);
        }
}

__global__ void __launch_bounds__(256) k_hmma1(const float* __restrict__ W1,
                                               const float* __restrict__ b1) {
    hmma_body<D_IN, D_HID, true, true>(g_agg1, W1, b1, g_h);
}
__global__ void __launch_bounds__(256) k_hmma2(const float* __restrict__ W2) {
    hmma_body<D_HID, D_OUT, false, false>(g_h, W2, nullptr, g_z);
}

// ---------------- final: agg2 + bias + log_softmax (proven) ----------------
__global__ void k_out(const float* __restrict__ b2, float* __restrict__ out) {
    int warp = (blockIdx.x * blockDim.x + threadIdx.x) >> 5;
    if (warp >= N_NODES) return;
    int lane = threadIdx.x & 31;
    int s0 = g_off[warp], s1 = g_off[warp + 1];
    float2 acc = make_float2(0.f, 0.f);
    for (int e = s0; e < s1; e++) {
        int s = g_csr[e];
        float2 v = *(const float2*)(g_z + (size_t)s * D_OUT + lane * 2);
        acc.x += v.x; acc.y += v.y;
    }
    float sc = 1.f / (float)max(s1 - s0, 1);
    float y0 = acc.x * sc + b2[lane * 2];
    float y1 = acc.y * sc + b2[lane * 2 + 1];
    float m = fmaxf(y0, y1);
#pragma unroll
    for (int o = 16; o; o >>= 1) m = fmaxf(m, __shfl_xor_sync(0xffffffffu, m, o));
    float se = expf(y0 - m) + expf(y1 - m);
#pragma unroll
    for (int o = 16; o; o >>= 1) se += __shfl_xor_sync(0xffffffffu, se, o);
    float lse = m + logf(se);
    float2 r = make_float2(y0 - lse, y1 - lse);
    *(float2*)(out + (size_t)warp * D_OUT + lane * 2) = r;
}

// ---------------- launch ----------------
extern "C" void kernel_launch(void* const* d_in, const int* in_sizes, int n_in,
                              void* d_out, int out_size) {
    const float* x  = (const float*)d_in[0];
    const void*  ei = d_in[1];
    const float* W1 = (const float*)d_in[2];
    const float* b1 = (const float*)d_in[3];
    const float* W2 = (const float*)d_in[4];
    const float* b2 = (const float*)d_in[5];
    float* out = (float*)d_out;

    k_detect<<<1, 1>>>((const int*)ei);
    k_zero <<<(N_NODES + 255) / 256, 256>>>();
    k_hist <<<(N_EDGES + 255) / 256, 256>>>(ei);
    k_scan1<<<SCAN_NB, 1024>>>();
    k_scan2<<<1, 128>>>();
    k_scan3<<<(N_NODES + 255) / 256, 256>>>();
    k_fill <<<(N_EDGES + 255) / 256, 256>>>(ei);

    k_agg1 <<<(N_NODES * 32 + 255) / 256, 256>>>(x);

    dim3 g1(M_PAD / 128, D_HID / 64);
    k_hmma1<<<g1, 256>>>(W1, b1);

    dim3 g2(M_PAD / 128, D_OUT / 64);
    k_hmma2<<<g2, 256>>>(W2);

    k_out  <<<(N_NODES * 32 + 255) / 256, 256>>>(b2, out);
}

// round 11
// speedup vs baseline: 1.0018x; 1.0018x over previous
#include <cuda_runtime.h>
#include <cuda_bf16.h>
#include <math.h>

#define N_NODES 100000
#define M_PAD   100096              // 782 * 128
#define D_IN    128
#define D_HID   256
#define D_OUT   64
#define N_EDGES 1600000
#define SCAN_NB ((N_NODES + 1023) / 1024)   // 98

typedef unsigned int       u32;
typedef unsigned long long u64;
typedef __nv_bfloat16      bf16;
typedef __nv_bfloat162     bf162;

// ---------------- scratch (static device globals; no allocation) ----------------
__device__ int   g_is64;
__device__ int   g_cnt[N_NODES];
__device__ int   g_cur[N_NODES];
__device__ int   g_off[N_NODES + 1];
__device__ int   g_bsum[128];
__device__ int   g_csr[N_EDGES];
__device__ float g_agg1[(size_t)M_PAD * D_IN];   // padded rows stay 0 (static init)
__device__ float g_h[(size_t)M_PAD * D_HID];
__device__ float g_z[(size_t)M_PAD * D_OUT];

// ---------------- helpers ----------------
__device__ __forceinline__ u32 smem_u32(const void* p) {
    u32 a;
    asm("{ .reg .u64 t; cvta.to.shared.u64 t, %1; cvt.u32.u64 %0, t; }" : "=r"(a) : "l"(p));
    return a;
}
__device__ __forceinline__ void split2(float v, bf16& h, bf16& l) {
    h = __float2bfloat16_rn(v);
    l = __float2bfloat16_rn(v - __bfloat162float(h));
}
__device__ __forceinline__ void ldsm4(u32* r, u32 addr) {
    asm volatile("ldmatrix.sync.aligned.m8n8.x4.shared.b16 {%0,%1,%2,%3}, [%4];"
        : "=r"(r[0]), "=r"(r[1]), "=r"(r[2]), "=r"(r[3]) : "r"(addr));
}
__device__ __forceinline__ void mma16816(float* c, const u32* a, u32 b0, u32 b1) {
    asm volatile(
        "mma.sync.aligned.m16n8k16.row.col.f32.bf16.bf16.f32 "
        "{%0,%1,%2,%3}, {%4,%5,%6,%7}, {%8,%9}, {%0,%1,%2,%3};"
        : "+f"(c[0]), "+f"(c[1]), "+f"(c[2]), "+f"(c[3])
        : "r"(a[0]), "r"(a[1]), "r"(a[2]), "r"(a[3]), "r"(b0), "r"(b1));
}

// edge index accessors (dtype decided at runtime)
__device__ __forceinline__ int edge_src(const void* ei, int i, int is64) {
    return is64 ? (int)((const long long*)ei)[i] : ((const int*)ei)[i];
}
__device__ __forceinline__ int edge_dst(const void* ei, int i, int is64) {
    return is64 ? (int)((const long long*)ei)[N_EDGES + i] : ((const int*)ei)[N_EDGES + i];
}

__global__ void k_detect(const int* __restrict__ ei_words) {
    int all_zero = 1;
    for (int i = 0; i < 64; i++)
        if (ei_words[2 * i + 1] != 0) { all_zero = 0; break; }
    g_is64 = all_zero;
}

// ---------------- CSR build ----------------
__global__ void k_zero() {
    int i = blockIdx.x * blockDim.x + threadIdx.x;
    if (i < N_NODES) { g_cnt[i] = 0; g_cur[i] = 0; }
}

__global__ void k_hist(const void* __restrict__ ei) {
    int is64 = g_is64;
    int i = blockIdx.x * blockDim.x + threadIdx.x;
    if (i < N_EDGES) {
        int d = edge_dst(ei, i, is64);
        if (d >= 0 && d < N_NODES) atomicAdd(&g_cnt[d], 1);
    }
}

__device__ __forceinline__ int warp_incl_scan(int x, int lane) {
#pragma unroll
    for (int o = 1; o < 32; o <<= 1) {
        int t = __shfl_up_sync(0xffffffffu, x, o);
        if (lane >= o) x += t;
    }
    return x;
}

__global__ void k_scan1() {
    int b = blockIdx.x, tid = threadIdx.x;
    int i = b * 1024 + tid;
    int v = (i < N_NODES) ? g_cnt[i] : 0;
    int lane = tid & 31, w = tid >> 5;
    int x = warp_incl_scan(v, lane);
    __shared__ int ws[32];
    if (lane == 31) ws[w] = x;
    __syncthreads();
    if (w == 0) {
        int t = ws[lane];
        t = warp_incl_scan(t, lane);
        ws[lane] = t;
    }
    __syncthreads();
    int incl = x + (w ? ws[w - 1] : 0);
    if (i < N_NODES) g_off[i] = incl - v;
    if (tid == 1023) g_bsum[b] = incl;
}

__global__ void k_scan2() {
    int tid = threadIdx.x, lane = tid & 31, w = tid >> 5;
    int v = (tid < SCAN_NB) ? g_bsum[tid] : 0;
    int x = warp_incl_scan(v, lane);
    __shared__ int ws[4];
    if (lane == 31) ws[w] = x;
    __syncthreads();
    int add = 0;
#pragma unroll
    for (int i = 0; i < 4; i++) if (i < w) add += ws[i];
    int incl = x + add;
    if (tid < SCAN_NB) g_bsum[tid] = incl - v;
}

__global__ void k_scan3() {
    int i = blockIdx.x * blockDim.x + threadIdx.x;
    if (i < N_NODES) g_off[i] += g_bsum[i >> 10];
    if (i == 0) g_off[N_NODES] = N_EDGES;
}

__global__ void k_fill(const void* __restrict__ ei) {
    int is64 = g_is64;
    int i = blockIdx.x * blockDim.x + threadIdx.x;
    if (i < N_EDGES) {
        int d = edge_dst(ei, i, is64);
        int s = edge_src(ei, i, is64);
        if (d >= 0 && d < N_NODES && s >= 0 && s < N_NODES) {
            int p = atomicAdd(&g_cur[d], 1);
            g_csr[g_off[d] + p] = s;
        }
    }
}

// ---------------- aggregation 1 (proven, fp32 out) ----------------
__global__ void k_agg1(const float* __restrict__ x) {
    int warp = (blockIdx.x * blockDim.x + threadIdx.x) >> 5;
    if (warp >= N_NODES) return;
    int lane = threadIdx.x & 31;
    int s0 = g_off[warp], s1 = g_off[warp + 1];
    float4 acc = make_float4(0.f, 0.f, 0.f, 0.f);
    for (int e = s0; e < s1; e++) {
        int s = g_csr[e];
        float4 v = *(const float4*)(x + (size_t)s * D_IN + lane * 4);
        acc.x += v.x; acc.y += v.y; acc.z += v.z; acc.w += v.w;
    }
    float sc = 1.f / (float)max(s1 - s0, 1);
    acc.x *= sc; acc.y *= sc; acc.z *= sc; acc.w *= sc;
    *(float4*)(g_agg1 + (size_t)warp * D_IN + lane * 4) = acc;
}

// ================= bf16 3-split tensor-core GEMM (in-kernel split) =================
// C[M_PAD, LDC] = A[M_PAD, KTOT] @ B[*, KTOT]^T (+bias, relu).
// fp32 in/out; hi/lo bf16 split done during staging. Tiles BM=128 BN=64 BK=32.
// 256 threads = 8 warps (4 m x 2 n). Single-buffered static smem (30.7 KB).
// NOTE: B tiles are stored n-major/k-contiguous, which IS the native col-major
// k x n fragment layout -> B fragments use NON-trans ldmatrix (fix vs round 7).
#define AST 40     // bf16 elems per A/B smem row (80 B, 16B-aligned rows)

template <int KTOT, int LDC, bool RELU, bool HASBIAS>
__device__ __forceinline__ void hmma_body(const float* __restrict__ A,
                                          const float* __restrict__ B,
                                          const float* __restrict__ bias,
                                          float* __restrict__ C) {
    __shared__ __align__(16) bf16 sAh[128 * AST];
    __shared__ __align__(16) bf16 sAl[128 * AST];
    __shared__ __align__(16) bf16 sBh[64 * AST];
    __shared__ __align__(16) bf16 sBl[64 * AST];

    const int tid  = threadIdx.x;
    const int wid  = tid >> 5;
    const int lane = tid & 31;
    const int g    = lane >> 2;
    const int tig  = lane & 3;
    const int m0   = blockIdx.x * 128;
    const int n0   = blockIdx.y * 64;
    const int wm   = (wid & 3) * 32;
    const int wn   = (wid >> 2) * 32;

    const u32 uAh = smem_u32(sAh), uAl = smem_u32(sAl);
    const u32 uBh = smem_u32(sBh), uBl = smem_u32(sBl);
    // per-lane ldmatrix addressing: row offset lane&15, col offset (lane>>4)*8
    const int lr = lane & 15;
    const int lc = (lane >> 4) << 3;

    float acc[2][4][4];
#pragma unroll
    for (int i = 0; i < 2; i++)
#pragma unroll
        for (int j = 0; j < 4; j++)
#pragma unroll
            for (int c = 0; c < 4; c++) acc[i][j][c] = 0.f;

    for (int kt = 0; kt < KTOT / 32; kt++) {
        const int k0 = kt * 32;
        __syncthreads();   // previous compute done before overwriting tiles
        // ---- stage A: 128 x 32 fp32 -> split -> sAh/sAl ----
#pragma unroll
        for (int i = 0; i < 4; i++) {
            int e = tid + i * 256;              // 0..1023
            int row = e >> 3, c4 = (e & 7) * 4;
            float4 v = *(const float4*)(A + (size_t)(m0 + row) * KTOT + k0 + c4);
            bf16 h0, l0, h1, l1, h2, l2, h3, l3;
            split2(v.x, h0, l0); split2(v.y, h1, l1);
            split2(v.z, h2, l2); split2(v.w, h3, l3);
            int o = row * AST + c4;
            *(bf162*)(sAh + o)     = bf162(h0, h1);
            *(bf162*)(sAh + o + 2) = bf162(h2, h3);
            *(bf162*)(sAl + o)     = bf162(l0, l1);
            *(bf162*)(sAl + o + 2) = bf162(l2, l3);
        }
        // ---- stage B: 64 x 32 fp32 -> split -> sBh/sBl ----
#pragma unroll
        for (int i = 0; i < 2; i++) {
            int e = tid + i * 256;              // 0..511
            int row = e >> 3, c4 = (e & 7) * 4;
            float4 v = *(const float4*)(B + (size_t)(n0 + row) * KTOT + k0 + c4);
            bf16 h0, l0, h1, l1, h2, l2, h3, l3;
            split2(v.x, h0, l0); split2(v.y, h1, l1);
            split2(v.z, h2, l2); split2(v.w, h3, l3);
            int o = row * AST + c4;
            *(bf162*)(sBh + o)     = bf162(h0, h1);
            *(bf162*)(sBh + o + 2) = bf162(h2, h3);
            *(bf162*)(sBl + o)     = bf162(l0, l1);
            *(bf162*)(sBl + o + 2) = bf162(l2, l3);
        }
        __syncthreads();

        // ---- compute: 2 k-slabs of 16, three compensation segments ----
#pragma unroll
        for (int ks = 0; ks < 2; ks++) {
            const int kc = ks * 16 + lc;
            u32 ah[2][4], al[2][4], bh[2][4], bl[2][4];
#pragma unroll
            for (int ma = 0; ma < 2; ma++) {
                u32 off = (u32)((wm + ma * 16 + lr) * AST + kc) * 2;
                ldsm4(ah[ma], uAh + off);
                ldsm4(al[ma], uAl + off);
            }
#pragma unroll
            for (int p = 0; p < 2; p++) {
                u32 off = (u32)((wn + p * 16 + lr) * AST + kc) * 2;
                ldsm4(bh[p], uBh + off);   // FIX: non-trans (k-contiguous rows
                ldsm4(bl[p], uBl + off);   // are already the col-major fragment)
            }
#pragma unroll
            for (int ma = 0; ma < 2; ma++)
#pragma unroll
                for (int nb = 0; nb < 4; nb++) {
                    int p = nb >> 1, j = nb & 1;
                    mma16816(acc[ma][nb], ah[ma], bh[p][j], bh[p][j + 2]);
                    mma16816(acc[ma][nb], al[ma], bh[p][j], bh[p][j + 2]);
                    mma16816(acc[ma][nb], ah[ma], bl[p][j], bl[p][j + 2]);
                }
        }
    }

    // ---- epilogue ----
#pragma unroll
    for (int ma = 0; ma < 2; ma++)
#pragma unroll
        for (int nb = 0; nb < 4; nb++) {
            int row = m0 + wm + ma * 16 + g;
            int col = n0 + wn + nb * 8 + 2 * tig;
            float c0 = acc[ma][nb][0], c1 = acc[ma][nb][1];
            float c2 = acc[ma][nb][2], c3 = acc[ma][nb][3];
            if (HASBIAS) {
                float bv0 = __ldg(bias + col), bv1 = __ldg(bias + col + 1);
                c0 += bv0; c1 += bv1; c2 += bv0; c3 += bv1;
            }
            if (RELU) {
                c0 = fmaxf(c0, 0.f); c1 = fmaxf(c1, 0.f);
                c2 = fmaxf(c2, 0.f); c3 = fmaxf(c3, 0.f);
            }
            *(float2*)(C + (size_t)row * LDC + col)       = make_float2(c0, c1);
            *(float2*)(C + (size_t)(row + 8) * LDC + col) = make_float2(c2, c3);
        }
}

__global__ void __launch_bounds__(256) k_hmma1(const float* __restrict__ W1,
                                               const float* __restrict__ b1) {
    hmma_body<D_IN, D_HID, true, true>(g_agg1, W1, b1, g_h);
}
__global__ void __launch_bounds__(256) k_hmma2(const float* __restrict__ W2) {
    hmma_body<D_HID, D_OUT, false, false>(g_h, W2, nullptr, g_z);
}

// ---------------- final: agg2 + bias + log_softmax (proven) ----------------
__global__ void k_out(const float* __restrict__ b2, float* __restrict__ out) {
    int warp = (blockIdx.x * blockDim.x + threadIdx.x) >> 5;
    if (warp >= N_NODES) return;
    int lane = threadIdx.x & 31;
    int s0 = g_off[warp], s1 = g_off[warp + 1];
    float2 acc = make_float2(0.f, 0.f);
    for (int e = s0; e < s1; e++) {
        int s = g_csr[e];
        float2 v = *(const float2*)(g_z + (size_t)s * D_OUT + lane * 2);
        acc.x += v.x; acc.y += v.y;
    }
    float sc = 1.f / (float)max(s1 - s0, 1);
    float y0 = acc.x * sc + b2[lane * 2];
    float y1 = acc.y * sc + b2[lane * 2 + 1];
    float m = fmaxf(y0, y1);
#pragma unroll
    for (int o = 16; o; o >>= 1) m = fmaxf(m, __shfl_xor_sync(0xffffffffu, m, o));
    float se = expf(y0 - m) + expf(y1 - m);
#pragma unroll
    for (int o = 16; o; o >>= 1) se += __shfl_xor_sync(0xffffffffu, se, o);
    float lse = m + logf(se);
    float2 r = make_float2(y0 - lse, y1 - lse);
    *(float2*)(out + (size_t)warp * D_OUT + lane * 2) = r;
}

// ---------------- launch ----------------
extern "C" void kernel_launch(void* const* d_in, const int* in_sizes, int n_in,
                              void* d_out, int out_size) {
    const float* x  = (const float*)d_in[0];
    const void*  ei = d_in[1];
    const float* W1 = (const float*)d_in[2];
    const float* b1 = (const float*)d_in[3];
    const float* W2 = (const float*)d_in[4];
    const float* b2 = (const float*)d_in[5];
    float* out = (float*)d_out;

    k_detect<<<1, 1>>>((const int*)ei);
    k_zero <<<(N_NODES + 255) / 256, 256>>>();
    k_hist <<<(N_EDGES + 255) / 256, 256>>>(ei);
    k_scan1<<<SCAN_NB, 1024>>>();
    k_scan2<<<1, 128>>>();
    k_scan3<<<(N_NODES + 255) / 256, 256>>>();
    k_fill <<<(N_EDGES + 255) / 256, 256>>>(ei);

    k_agg1 <<<(N_NODES * 32 + 255) / 256, 256>>>(x);

    dim3 g1(M_PAD / 128, D_HID / 64);
    k_hmma1<<<g1, 256>>>(W1, b1);

    dim3 g2(M_PAD / 128, D_OUT / 64);
    k_hmma2<<<g2, 256>>>(W2);

    k_out  <<<(N_NODES * 32 + 255) / 256, 256>>>(b2, out);
}

// round 12
// speedup vs baseline: 1.0659x; 1.0640x over previous
#include <cuda_runtime.h>
#include <cuda_bf16.h>
#include <math.h>

#define N_NODES 100000
#define M_PAD   100096              // 782 * 128
#define D_IN    128
#define D_HID   256
#define D_OUT   64
#define N_EDGES 1600000
#define SCAN_NB ((N_NODES + 1023) / 1024)   // 98

typedef unsigned int       u32;
typedef unsigned long long u64;
typedef __nv_bfloat16      bf16;
typedef __nv_bfloat162     bf162;

// ---------------- scratch (static device globals; no allocation) ----------------
__device__ int   g_is64;
__device__ int   g_cnt[N_NODES];
__device__ int   g_cur[N_NODES];
__device__ int   g_off[N_NODES + 1];
__device__ int   g_bsum[128];
__device__ int   g_csr[N_EDGES];
__device__ bf16  g_xb[(size_t)N_NODES * D_IN];   // bf16 copy of x
__device__ float g_agg1[(size_t)M_PAD * D_IN];   // padded rows stay 0 (static init)
__device__ float g_h[(size_t)M_PAD * D_HID];
__device__ bf16  g_zb[(size_t)M_PAD * D_OUT];    // layer-2 pre-agg logits, bf16

// ---------------- helpers ----------------
__device__ __forceinline__ u32 smem_u32(const void* p) {
    u32 a;
    asm("{ .reg .u64 t; cvta.to.shared.u64 t, %1; cvt.u32.u64 %0, t; }" : "=r"(a) : "l"(p));
    return a;
}
__device__ __forceinline__ void split2(float v, bf16& h, bf16& l) {
    h = __float2bfloat16_rn(v);
    l = __float2bfloat16_rn(v - __bfloat162float(h));
}
__device__ __forceinline__ void ldsm4(u32* r, u32 addr) {
    asm volatile("ldmatrix.sync.aligned.m8n8.x4.shared.b16 {%0,%1,%2,%3}, [%4];"
        : "=r"(r[0]), "=r"(r[1]), "=r"(r[2]), "=r"(r[3]) : "r"(addr));
}
__device__ __forceinline__ void mma16816(float* c, const u32* a, u32 b0, u32 b1) {
    asm volatile(
        "mma.sync.aligned.m16n8k16.row.col.f32.bf16.bf16.f32 "
        "{%0,%1,%2,%3}, {%4,%5,%6,%7}, {%8,%9}, {%0,%1,%2,%3};"
        : "+f"(c[0]), "+f"(c[1]), "+f"(c[2]), "+f"(c[3])
        : "r"(a[0]), "r"(a[1]), "r"(a[2]), "r"(a[3]), "r"(b0), "r"(b1));
}

// edge index accessors (dtype decided at runtime)
__device__ __forceinline__ int edge_src(const void* ei, int i, int is64) {
    return is64 ? (int)((const long long*)ei)[i] : ((const int*)ei)[i];
}
__device__ __forceinline__ int edge_dst(const void* ei, int i, int is64) {
    return is64 ? (int)((const long long*)ei)[N_EDGES + i] : ((const int*)ei)[N_EDGES + i];
}

__global__ void k_detect(const int* __restrict__ ei_words) {
    int all_zero = 1;
    for (int i = 0; i < 64; i++)
        if (ei_words[2 * i + 1] != 0) { all_zero = 0; break; }
    g_is64 = all_zero;
}

// ---------------- CSR build ----------------
__global__ void k_zero() {
    int i = blockIdx.x * blockDim.x + threadIdx.x;
    if (i < N_NODES) { g_cnt[i] = 0; g_cur[i] = 0; }
}

__global__ void k_hist(const void* __restrict__ ei) {
    int is64 = g_is64;
    int i = blockIdx.x * blockDim.x + threadIdx.x;
    if (i < N_EDGES) {
        int d = edge_dst(ei, i, is64);
        if (d >= 0 && d < N_NODES) atomicAdd(&g_cnt[d], 1);
    }
}

__device__ __forceinline__ int warp_incl_scan(int x, int lane) {
#pragma unroll
    for (int o = 1; o < 32; o <<= 1) {
        int t = __shfl_up_sync(0xffffffffu, x, o);
        if (lane >= o) x += t;
    }
    return x;
}

__global__ void k_scan1() {
    int b = blockIdx.x, tid = threadIdx.x;
    int i = b * 1024 + tid;
    int v = (i < N_NODES) ? g_cnt[i] : 0;
    int lane = tid & 31, w = tid >> 5;
    int x = warp_incl_scan(v, lane);
    __shared__ int ws[32];
    if (lane == 31) ws[w] = x;
    __syncthreads();
    if (w == 0) {
        int t = ws[lane];
        t = warp_incl_scan(t, lane);
        ws[lane] = t;
    }
    __syncthreads();
    int incl = x + (w ? ws[w - 1] : 0);
    if (i < N_NODES) g_off[i] = incl - v;
    if (tid == 1023) g_bsum[b] = incl;
}

__global__ void k_scan2() {
    int tid = threadIdx.x, lane = tid & 31, w = tid >> 5;
    int v = (tid < SCAN_NB) ? g_bsum[tid] : 0;
    int x = warp_incl_scan(v, lane);
    __shared__ int ws[4];
    if (lane == 31) ws[w] = x;
    __syncthreads();
    int add = 0;
#pragma unroll
    for (int i = 0; i < 4; i++) if (i < w) add += ws[i];
    int incl = x + add;
    if (tid < SCAN_NB) g_bsum[tid] = incl - v;
}

__global__ void k_scan3() {
    int i = blockIdx.x * blockDim.x + threadIdx.x;
    if (i < N_NODES) g_off[i] += g_bsum[i >> 10];
    if (i == 0) g_off[N_NODES] = N_EDGES;
}

__global__ void k_fill(const void* __restrict__ ei) {
    int is64 = g_is64;
    int i = blockIdx.x * blockDim.x + threadIdx.x;
    if (i < N_EDGES) {
        int d = edge_dst(ei, i, is64);
        int s = edge_src(ei, i, is64);
        if (d >= 0 && d < N_NODES && s >= 0 && s < N_NODES) {
            int p = atomicAdd(&g_cur[d], 1);
            g_csr[g_off[d] + p] = s;
        }
    }
}

// ---------------- x -> bf16 conversion ----------------
__global__ void k_xcvt(const float* __restrict__ x) {
    int i = blockIdx.x * blockDim.x + threadIdx.x;   // one float4 per thread
    if (i < N_NODES * D_IN / 4) {
        float4 v = ((const float4*)x)[i];
        *(bf162*)(g_xb + (size_t)i * 4)     = bf162(__float2bfloat16_rn(v.x), __float2bfloat16_rn(v.y));
        *(bf162*)(g_xb + (size_t)i * 4 + 2) = bf162(__float2bfloat16_rn(v.z), __float2bfloat16_rn(v.w));
    }
}

// ---------------- aggregation 1: mean over in-neighbors of bf16 x, fp32 out ----------------
__global__ void k_agg1() {
    int warp = (blockIdx.x * blockDim.x + threadIdx.x) >> 5;
    if (warp >= N_NODES) return;
    int lane = threadIdx.x & 31;
    int s0 = g_off[warp], s1 = g_off[warp + 1];
    float4 acc = make_float4(0.f, 0.f, 0.f, 0.f);
    for (int e = s0; e < s1; e++) {
        int s = g_csr[e];
        // lane covers 4 dims = 8 bytes = 2 x bf162
        const bf162* p = (const bf162*)(g_xb + (size_t)s * D_IN + lane * 4);
        float2 f0 = __bfloat1622float2(p[0]);
        float2 f1 = __bfloat1622float2(p[1]);
        acc.x += f0.x; acc.y += f0.y; acc.z += f1.x; acc.w += f1.y;
    }
    float sc = 1.f / (float)max(s1 - s0, 1);
    acc.x *= sc; acc.y *= sc; acc.z *= sc; acc.w *= sc;
    *(float4*)(g_agg1 + (size_t)warp * D_IN + lane * 4) = acc;
}

// ================= bf16 2-term tensor-core GEMM (A split hi/lo, B plain bf16) =================
// C[M_PAD, LDC] = A[M_PAD, KTOT] @ B[*, KTOT]^T (+bias, relu). Output fp32 or bf16.
// Tiles BM=128 BN=64 BK=32; 256 threads = 8 warps (4 m x 2 n). Single-buffered smem.
// B tiles stored n-major/k-contiguous == native col-major fragment -> NON-trans ldmatrix.
#define AST 40     // bf16 elems per A/B smem row (80 B, 16B-aligned rows)

template <int KTOT, int LDC, bool RELU, bool HASBIAS, bool OUTBF16>
__device__ __forceinline__ void hmma_body(const float* __restrict__ A,
                                          const float* __restrict__ B,
                                          const float* __restrict__ bias,
                                          float* __restrict__ Cf,
                                          bf16* __restrict__ Cb) {
    __shared__ __align__(16) bf16 sAh[128 * AST];
    __shared__ __align__(16) bf16 sAl[128 * AST];
    __shared__ __align__(16) bf16 sBh[64 * AST];

    const int tid  = threadIdx.x;
    const int wid  = tid >> 5;
    const int lane = tid & 31;
    const int g    = lane >> 2;
    const int tig  = lane & 3;
    const int m0   = blockIdx.x * 128;
    const int n0   = blockIdx.y * 64;
    const int wm   = (wid & 3) * 32;
    const int wn   = (wid >> 2) * 32;

    const u32 uAh = smem_u32(sAh), uAl = smem_u32(sAl);
    const u32 uBh = smem_u32(sBh);
    const int lr = lane & 15;
    const int lc = (lane >> 4) << 3;

    float acc[2][4][4];
#pragma unroll
    for (int i = 0; i < 2; i++)
#pragma unroll
        for (int j = 0; j < 4; j++)
#pragma unroll
            for (int c = 0; c < 4; c++) acc[i][j][c] = 0.f;

    for (int kt = 0; kt < KTOT / 32; kt++) {
        const int k0 = kt * 32;
        __syncthreads();
        // ---- stage A: 128 x 32 fp32 -> split hi/lo ----
#pragma unroll
        for (int i = 0; i < 4; i++) {
            int e = tid + i * 256;
            int row = e >> 3, c4 = (e & 7) * 4;
            float4 v = *(const float4*)(A + (size_t)(m0 + row) * KTOT + k0 + c4);
            bf16 h0, l0, h1, l1, h2, l2, h3, l3;
            split2(v.x, h0, l0); split2(v.y, h1, l1);
            split2(v.z, h2, l2); split2(v.w, h3, l3);
            int o = row * AST + c4;
            *(bf162*)(sAh + o)     = bf162(h0, h1);
            *(bf162*)(sAh + o + 2) = bf162(h2, h3);
            *(bf162*)(sAl + o)     = bf162(l0, l1);
            *(bf162*)(sAl + o + 2) = bf162(l2, l3);
        }
        // ---- stage B: 64 x 32 fp32 -> plain bf16 (rn) ----
#pragma unroll
        for (int i = 0; i < 2; i++) {
            int e = tid + i * 256;
            int row = e >> 3, c4 = (e & 7) * 4;
            float4 v = *(const float4*)(B + (size_t)(n0 + row) * KTOT + k0 + c4);
            int o = row * AST + c4;
            *(bf162*)(sBh + o)     = bf162(__float2bfloat16_rn(v.x), __float2bfloat16_rn(v.y));
            *(bf162*)(sBh + o + 2) = bf162(__float2bfloat16_rn(v.z), __float2bfloat16_rn(v.w));
        }
        __syncthreads();

        // ---- compute: 2 k-slabs of 16, two compensation segments ----
#pragma unroll
        for (int ks = 0; ks < 2; ks++) {
            const int kc = ks * 16 + lc;
            u32 ah[2][4], al[2][4], bh[2][4];
#pragma unroll
            for (int ma = 0; ma < 2; ma++) {
                u32 off = (u32)((wm + ma * 16 + lr) * AST + kc) * 2;
                ldsm4(ah[ma], uAh + off);
                ldsm4(al[ma], uAl + off);
            }
#pragma unroll
            for (int p = 0; p < 2; p++) {
                u32 off = (u32)((wn + p * 16 + lr) * AST + kc) * 2;
                ldsm4(bh[p], uBh + off);
            }
#pragma unroll
            for (int ma = 0; ma < 2; ma++)
#pragma unroll
                for (int nb = 0; nb < 4; nb++) {
                    int p = nb >> 1, j = nb & 1;
                    mma16816(acc[ma][nb], ah[ma], bh[p][j], bh[p][j + 2]);
                    mma16816(acc[ma][nb], al[ma], bh[p][j], bh[p][j + 2]);
                }
        }
    }

    // ---- epilogue ----
#pragma unroll
    for (int ma = 0; ma < 2; ma++)
#pragma unroll
        for (int nb = 0; nb < 4; nb++) {
            int row = m0 + wm + ma * 16 + g;
            int col = n0 + wn + nb * 8 + 2 * tig;
            float c0 = acc[ma][nb][0], c1 = acc[ma][nb][1];
            float c2 = acc[ma][nb][2], c3 = acc[ma][nb][3];
            if (HASBIAS) {
                float bv0 = __ldg(bias + col), bv1 = __ldg(bias + col + 1);
                c0 += bv0; c1 += bv1; c2 += bv0; c3 += bv1;
            }
            if (RELU) {
                c0 = fmaxf(c0, 0.f); c1 = fmaxf(c1, 0.f);
                c2 = fmaxf(c2, 0.f); c3 = fmaxf(c3, 0.f);
            }
            if (OUTBF16) {
                *(bf162*)(Cb + (size_t)row * LDC + col) =
                    bf162(__float2bfloat16_rn(c0), __float2bfloat16_rn(c1));
                *(bf162*)(Cb + (size_t)(row + 8) * LDC + col) =
                    bf162(__float2bfloat16_rn(c2), __float2bfloat16_rn(c3));
            } else {
                *(float2*)(Cf + (size_t)row * LDC + col)       = make_float2(c0, c1);
                *(float2*)(Cf + (size_t)(row + 8) * LDC + col) = make_float2(c2, c3);
            }
        }
}

__global__ void __launch_bounds__(256) k_hmma1(const float* __restrict__ W1,
                                               const float* __restrict__ b1) {
    hmma_body<D_IN, D_HID, true, true, false>(g_agg1, W1, b1, g_h, nullptr);
}
__global__ void __launch_bounds__(256) k_hmma2(const float* __restrict__ W2) {
    hmma_body<D_HID, D_OUT, false, false, true>(g_h, W2, nullptr, nullptr, g_zb);
}

// ---------------- final: agg2 (bf16 z) + bias + log_softmax ----------------
__global__ void k_out(const float* __restrict__ b2, float* __restrict__ out) {
    int warp = (blockIdx.x * blockDim.x + threadIdx.x) >> 5;
    if (warp >= N_NODES) return;
    int lane = threadIdx.x & 31;
    int s0 = g_off[warp], s1 = g_off[warp + 1];
    float2 acc = make_float2(0.f, 0.f);
    for (int e = s0; e < s1; e++) {
        int s = g_csr[e];
        bf162 v = *(const bf162*)(g_zb + (size_t)s * D_OUT + lane * 2);
        float2 f = __bfloat1622float2(v);
        acc.x += f.x; acc.y += f.y;
    }
    float sc = 1.f / (float)max(s1 - s0, 1);
    float y0 = acc.x * sc + b2[lane * 2];
    float y1 = acc.y * sc + b2[lane * 2 + 1];
    float m = fmaxf(y0, y1);
#pragma unroll
    for (int o = 16; o; o >>= 1) m = fmaxf(m, __shfl_xor_sync(0xffffffffu, m, o));
    float se = expf(y0 - m) + expf(y1 - m);
#pragma unroll
    for (int o = 16; o; o >>= 1) se += __shfl_xor_sync(0xffffffffu, se, o);
    float lse = m + logf(se);
    float2 r = make_float2(y0 - lse, y1 - lse);
    *(float2*)(out + (size_t)warp * D_OUT + lane * 2) = r;
}

// ---------------- launch ----------------
extern "C" void kernel_launch(void* const* d_in, const int* in_sizes, int n_in,
                              void* d_out, int out_size) {
    const float* x  = (const float*)d_in[0];
    const void*  ei = d_in[1];
    const float* W1 = (const float*)d_in[2];
    const float* b1 = (const float*)d_in[3];
    const float* W2 = (const float*)d_in[4];
    const float* b2 = (const float*)d_in[5];
    float* out = (float*)d_out;

    k_detect<<<1, 1>>>((const int*)ei);
    k_zero <<<(N_NODES + 255) / 256, 256>>>();
    k_hist <<<(N_EDGES + 255) / 256, 256>>>(ei);
    k_xcvt <<<(N_NODES * D_IN / 4 + 255) / 256, 256>>>(x);
    k_scan1<<<SCAN_NB, 1024>>>();
    k_scan2<<<1, 128>>>();
    k_scan3<<<(N_NODES + 255) / 256, 256>>>();
    k_fill <<<(N_EDGES + 255) / 256, 256>>>(ei);

    k_agg1 <<<(N_NODES * 32 + 255) / 256, 256>>>();

    dim3 g1(M_PAD / 128, D_HID / 64);
    k_hmma1<<<g1, 256>>>(W1, b1);

    dim3 g2(M_PAD / 128, D_OUT / 64);
    k_hmma2<<<g2, 256>>>(W2);

    k_out  <<<(N_NODES * 32 + 255) / 256, 256>>>(b2, out);
}

// round 13
// speedup vs baseline: 1.2665x; 1.1882x over previous
#include <cuda_runtime.h>
#include <cuda_bf16.h>
#include <math.h>

#define N_NODES 100000
#define M_PAD   100096              // 782 * 128
#define D_IN    128
#define D_HID   256
#define D_OUT   64
#define N_EDGES 1600000
#define SCAN_NB ((N_NODES + 1023) / 1024)   // 98

typedef unsigned int       u32;
typedef unsigned long long u64;
typedef __nv_bfloat16      bf16;
typedef __nv_bfloat162     bf162;

// ---------------- scratch (static device globals; no allocation) ----------------
__device__ int   g_is64;
__device__ int   g_cnt[N_NODES];
__device__ int   g_cur[N_NODES];
__device__ int   g_off[N_NODES + 1];
__device__ int   g_bsum[128];
__device__ int   g_csr[N_EDGES];
__device__ bf16  g_xb[(size_t)N_NODES * D_IN];    // bf16 copy of x
__device__ bf16  g_a1b[(size_t)M_PAD * D_IN];     // agg1 result, bf16 (padded rows stay 0)
__device__ bf16  g_hb[(size_t)M_PAD * D_HID];     // layer-1 output, bf16
__device__ bf16  g_zb[(size_t)M_PAD * D_OUT];     // layer-2 pre-agg logits, bf16

// ---------------- helpers ----------------
__device__ __forceinline__ u32 smem_u32(const void* p) {
    u32 a;
    asm("{ .reg .u64 t; cvta.to.shared.u64 t, %1; cvt.u32.u64 %0, t; }" : "=r"(a) : "l"(p));
    return a;
}
__device__ __forceinline__ void ldsm4(u32* r, u32 addr) {
    asm volatile("ldmatrix.sync.aligned.m8n8.x4.shared.b16 {%0,%1,%2,%3}, [%4];"
        : "=r"(r[0]), "=r"(r[1]), "=r"(r[2]), "=r"(r[3]) : "r"(addr));
}
__device__ __forceinline__ void mma16816(float* c, const u32* a, u32 b0, u32 b1) {
    asm volatile(
        "mma.sync.aligned.m16n8k16.row.col.f32.bf16.bf16.f32 "
        "{%0,%1,%2,%3}, {%4,%5,%6,%7}, {%8,%9}, {%0,%1,%2,%3};"
        : "+f"(c[0]), "+f"(c[1]), "+f"(c[2]), "+f"(c[3])
        : "r"(a[0]), "r"(a[1]), "r"(a[2]), "r"(a[3]), "r"(b0), "r"(b1));
}

// edge index accessors (dtype decided at runtime)
__device__ __forceinline__ int edge_src(const void* ei, int i, int is64) {
    return is64 ? (int)((const long long*)ei)[i] : ((const int*)ei)[i];
}
__device__ __forceinline__ int edge_dst(const void* ei, int i, int is64) {
    return is64 ? (int)((const long long*)ei)[N_EDGES + i] : ((const int*)ei)[N_EDGES + i];
}

__global__ void k_detect(const int* __restrict__ ei_words) {
    int all_zero = 1;
    for (int i = 0; i < 64; i++)
        if (ei_words[2 * i + 1] != 0) { all_zero = 0; break; }
    g_is64 = all_zero;
}

// ---------------- CSR build ----------------
__global__ void k_zero() {
    int i = blockIdx.x * blockDim.x + threadIdx.x;
    if (i < N_NODES) { g_cnt[i] = 0; g_cur[i] = 0; }
}

__global__ void k_hist(const void* __restrict__ ei) {
    int is64 = g_is64;
    int i = blockIdx.x * blockDim.x + threadIdx.x;
    if (i < N_EDGES) {
        int d = edge_dst(ei, i, is64);
        if (d >= 0 && d < N_NODES) atomicAdd(&g_cnt[d], 1);
    }
}

__device__ __forceinline__ int warp_incl_scan(int x, int lane) {
#pragma unroll
    for (int o = 1; o < 32; o <<= 1) {
        int t = __shfl_up_sync(0xffffffffu, x, o);
        if (lane >= o) x += t;
    }
    return x;
}

__global__ void k_scan1() {
    int b = blockIdx.x, tid = threadIdx.x;
    int i = b * 1024 + tid;
    int v = (i < N_NODES) ? g_cnt[i] : 0;
    int lane = tid & 31, w = tid >> 5;
    int x = warp_incl_scan(v, lane);
    __shared__ int ws[32];
    if (lane == 31) ws[w] = x;
    __syncthreads();
    if (w == 0) {
        int t = ws[lane];
        t = warp_incl_scan(t, lane);
        ws[lane] = t;
    }
    __syncthreads();
    int incl = x + (w ? ws[w - 1] : 0);
    if (i < N_NODES) g_off[i] = incl - v;
    if (tid == 1023) g_bsum[b] = incl;
}

__global__ void k_scan2() {
    int tid = threadIdx.x, lane = tid & 31, w = tid >> 5;
    int v = (tid < SCAN_NB) ? g_bsum[tid] : 0;
    int x = warp_incl_scan(v, lane);
    __shared__ int ws[4];
    if (lane == 31) ws[w] = x;
    __syncthreads();
    int add = 0;
#pragma unroll
    for (int i = 0; i < 4; i++) if (i < w) add += ws[i];
    int incl = x + add;
    if (tid < SCAN_NB) g_bsum[tid] = incl - v;
}

__global__ void k_scan3() {
    int i = blockIdx.x * blockDim.x + threadIdx.x;
    if (i < N_NODES) g_off[i] += g_bsum[i >> 10];
    if (i == 0) g_off[N_NODES] = N_EDGES;
}

__global__ void k_fill(const void* __restrict__ ei) {
    int is64 = g_is64;
    int i = blockIdx.x * blockDim.x + threadIdx.x;
    if (i < N_EDGES) {
        int d = edge_dst(ei, i, is64);
        int s = edge_src(ei, i, is64);
        if (d >= 0 && d < N_NODES && s >= 0 && s < N_NODES) {
            int p = atomicAdd(&g_cur[d], 1);
            g_csr[g_off[d] + p] = s;
        }
    }
}

// ---------------- x -> bf16 conversion ----------------
__global__ void k_xcvt(const float* __restrict__ x) {
    int i = blockIdx.x * blockDim.x + threadIdx.x;   // one float4 per thread
    if (i < N_NODES * D_IN / 4) {
        float4 v = ((const float4*)x)[i];
        *(bf162*)(g_xb + (size_t)i * 4)     = bf162(__float2bfloat16_rn(v.x), __float2bfloat16_rn(v.y));
        *(bf162*)(g_xb + (size_t)i * 4 + 2) = bf162(__float2bfloat16_rn(v.z), __float2bfloat16_rn(v.w));
    }
}

// ---------------- aggregation 1: mean over in-neighbors of bf16 x, bf16 out ----------------
__global__ void k_agg1() {
    int warp = (blockIdx.x * blockDim.x + threadIdx.x) >> 5;
    if (warp >= N_NODES) return;
    int lane = threadIdx.x & 31;
    int s0 = g_off[warp], s1 = g_off[warp + 1];
    float4 acc = make_float4(0.f, 0.f, 0.f, 0.f);
    int e = s0;
    for (; e + 2 <= s1; e += 2) {            // 2-way unroll for MLP
        int sa = g_csr[e], sb = g_csr[e + 1];
        const bf162* pa = (const bf162*)(g_xb + (size_t)sa * D_IN + lane * 4);
        const bf162* pb = (const bf162*)(g_xb + (size_t)sb * D_IN + lane * 4);
        bf162 a0 = pa[0], a1 = pa[1], b0 = pb[0], b1 = pb[1];
        float2 f;
        f = __bfloat1622float2(a0); acc.x += f.x; acc.y += f.y;
        f = __bfloat1622float2(a1); acc.z += f.x; acc.w += f.y;
        f = __bfloat1622float2(b0); acc.x += f.x; acc.y += f.y;
        f = __bfloat1622float2(b1); acc.z += f.x; acc.w += f.y;
    }
    if (e < s1) {
        int s = g_csr[e];
        const bf162* p = (const bf162*)(g_xb + (size_t)s * D_IN + lane * 4);
        float2 f0 = __bfloat1622float2(p[0]);
        float2 f1 = __bfloat1622float2(p[1]);
        acc.x += f0.x; acc.y += f0.y; acc.z += f1.x; acc.w += f1.y;
    }
    float sc = 1.f / (float)max(s1 - s0, 1);
    bf162 o0(__float2bfloat16_rn(acc.x * sc), __float2bfloat16_rn(acc.y * sc));
    bf162 o1(__float2bfloat16_rn(acc.z * sc), __float2bfloat16_rn(acc.w * sc));
    bf162* q = (bf162*)(g_a1b + (size_t)warp * D_IN + lane * 4);
    q[0] = o0; q[1] = o1;
}

// ================= plain bf16 tensor-core GEMM =================
// C[M_PAD, LDC] = A[M_PAD, KTOT](bf16) @ B[*, KTOT](fp32->bf16)^T (+bias, relu), bf16 out.
// Tiles BM=128 BN=64 BK=32; 256 threads = 8 warps (4 m x 2 n). Single-buffered smem.
// B tiles stored n-major/k-contiguous == native col-major fragment -> NON-trans ldmatrix.
#define AST 40     // bf16 elems per A/B smem row (80 B, 16B-aligned rows)

template <int KTOT, int LDC, bool RELU, bool HASBIAS>
__device__ __forceinline__ void hmma_body(const bf16* __restrict__ A,
                                          const float* __restrict__ B,
                                          const float* __restrict__ bias,
                                          bf16* __restrict__ C) {
    __shared__ __align__(16) bf16 sA[128 * AST];
    __shared__ __align__(16) bf16 sB[64 * AST];

    const int tid  = threadIdx.x;
    const int wid  = tid >> 5;
    const int lane = tid & 31;
    const int g    = lane >> 2;
    const int tig  = lane & 3;
    const int m0   = blockIdx.x * 128;
    const int n0   = blockIdx.y * 64;
    const int wm   = (wid & 3) * 32;
    const int wn   = (wid >> 2) * 32;

    const u32 uA = smem_u32(sA);
    const u32 uB = smem_u32(sB);
    const int lr = lane & 15;
    const int lc = (lane >> 4) << 3;

    float acc[2][4][4];
#pragma unroll
    for (int i = 0; i < 2; i++)
#pragma unroll
        for (int j = 0; j < 4; j++)
#pragma unroll
            for (int c = 0; c < 4; c++) acc[i][j][c] = 0.f;

    for (int kt = 0; kt < KTOT / 32; kt++) {
        const int k0 = kt * 32;
        __syncthreads();
        // ---- stage A: 128 x 32 bf16 raw copy (16B per thread, 2 iters) ----
#pragma unroll
        for (int i = 0; i < 2; i++) {
            int e = tid + i * 256;              // 0..511
            int row = e >> 2, c8 = (e & 3) * 8;
            *(uint4*)(sA + row * AST + c8) =
                *(const uint4*)(A + (size_t)(m0 + row) * KTOT + k0 + c8);
        }
        // ---- stage B: 64 x 32 fp32 -> bf16 (rn) ----
#pragma unroll
        for (int i = 0; i < 2; i++) {
            int e = tid + i * 256;              // 0..511
            int row = e >> 3, c4 = (e & 7) * 4;
            float4 v = *(const float4*)(B + (size_t)(n0 + row) * KTOT + k0 + c4);
            int o = row * AST + c4;
            *(bf162*)(sB + o)     = bf162(__float2bfloat16_rn(v.x), __float2bfloat16_rn(v.y));
            *(bf162*)(sB + o + 2) = bf162(__float2bfloat16_rn(v.z), __float2bfloat16_rn(v.w));
        }
        __syncthreads();

        // ---- compute: 2 k-slabs of 16 ----
#pragma unroll
        for (int ks = 0; ks < 2; ks++) {
            const int kc = ks * 16 + lc;
            u32 ah[2][4], bh[2][4];
#pragma unroll
            for (int ma = 0; ma < 2; ma++) {
                u32 off = (u32)((wm + ma * 16 + lr) * AST + kc) * 2;
                ldsm4(ah[ma], uA + off);
            }
#pragma unroll
            for (int p = 0; p < 2; p++) {
                u32 off = (u32)((wn + p * 16 + lr) * AST + kc) * 2;
                ldsm4(bh[p], uB + off);
            }
#pragma unroll
            for (int ma = 0; ma < 2; ma++)
#pragma unroll
                for (int nb = 0; nb < 4; nb++) {
                    int p = nb >> 1, j = nb & 1;
                    mma16816(acc[ma][nb], ah[ma], bh[p][j], bh[p][j + 2]);
                }
        }
    }

    // ---- epilogue: bf16 out ----
#pragma unroll
    for (int ma = 0; ma < 2; ma++)
#pragma unroll
        for (int nb = 0; nb < 4; nb++) {
            int row = m0 + wm + ma * 16 + g;
            int col = n0 + wn + nb * 8 + 2 * tig;
            float c0 = acc[ma][nb][0], c1 = acc[ma][nb][1];
            float c2 = acc[ma][nb][2], c3 = acc[ma][nb][3];
            if (HASBIAS) {
                float bv0 = __ldg(bias + col), bv1 = __ldg(bias + col + 1);
                c0 += bv0; c1 += bv1; c2 += bv0; c3 += bv1;
            }
            if (RELU) {
                c0 = fmaxf(c0, 0.f); c1 = fmaxf(c1, 0.f);
                c2 = fmaxf(c2, 0.f); c3 = fmaxf(c3, 0.f);
            }
            *(bf162*)(C + (size_t)row * LDC + col) =
                bf162(__float2bfloat16_rn(c0), __float2bfloat16_rn(c1));
            *(bf162*)(C + (size_t)(row + 8) * LDC + col) =
                bf162(__float2bfloat16_rn(c2), __float2bfloat16_rn(c3));
        }
}

__global__ void __launch_bounds__(256) k_hmma1(const float* __restrict__ W1,
                                               const float* __restrict__ b1) {
    hmma_body<D_IN, D_HID, true, true>(g_a1b, W1, b1, g_hb);
}
__global__ void __launch_bounds__(256) k_hmma2(const float* __restrict__ W2) {
    hmma_body<D_HID, D_OUT, false, false>(g_hb, W2, nullptr, g_zb);
}

// ---------------- final: agg2 (bf16 z) + bias + log_softmax ----------------
__global__ void k_out(const float* __restrict__ b2, float* __restrict__ out) {
    int warp = (blockIdx.x * blockDim.x + threadIdx.x) >> 5;
    if (warp >= N_NODES) return;
    int lane = threadIdx.x & 31;
    int s0 = g_off[warp], s1 = g_off[warp + 1];
    float2 acc = make_float2(0.f, 0.f);
    int e = s0;
    for (; e + 2 <= s1; e += 2) {            // 2-way unroll for MLP
        int sa = g_csr[e], sb = g_csr[e + 1];
        bf162 va = *(const bf162*)(g_zb + (size_t)sa * D_OUT + lane * 2);
        bf162 vb = *(const bf162*)(g_zb + (size_t)sb * D_OUT + lane * 2);
        float2 fa = __bfloat1622float2(va);
        float2 fb = __bfloat1622float2(vb);
        acc.x += fa.x + fb.x; acc.y += fa.y + fb.y;
    }
    if (e < s1) {
        int s = g_csr[e];
        float2 f = __bfloat1622float2(*(const bf162*)(g_zb + (size_t)s * D_OUT + lane * 2));
        acc.x += f.x; acc.y += f.y;
    }
    float sc = 1.f / (float)max(s1 - s0, 1);
    float y0 = acc.x * sc + b2[lane * 2];
    float y1 = acc.y * sc + b2[lane * 2 + 1];
    float m = fmaxf(y0, y1);
#pragma unroll
    for (int o = 16; o; o >>= 1) m = fmaxf(m, __shfl_xor_sync(0xffffffffu, m, o));
    float se = expf(y0 - m) + expf(y1 - m);
#pragma unroll
    for (int o = 16; o; o >>= 1) se += __shfl_xor_sync(0xffffffffu, se, o);
    float lse = m + logf(se);
    float2 r = make_float2(y0 - lse, y1 - lse);
    *(float2*)(out + (size_t)warp * D_OUT + lane * 2) = r;
}

// ---------------- launch ----------------
extern "C" void kernel_launch(void* const* d_in, const int* in_sizes, int n_in,
                              void* d_out, int out_size) {
    const float* x  = (const float*)d_in[0];
    const void*  ei = d_in[1];
    const float* W1 = (const float*)d_in[2];
    const float* b1 = (const float*)d_in[3];
    const float* W2 = (const float*)d_in[4];
    const float* b2 = (const float*)d_in[5];
    float* out = (float*)d_out;

    k_detect<<<1, 1>>>((const int*)ei);
    k_zero <<<(N_NODES + 255) / 256, 256>>>();
    k_hist <<<(N_EDGES + 255) / 256, 256>>>(ei);
    k_xcvt <<<(N_NODES * D_IN / 4 + 255) / 256, 256>>>(x);
    k_scan1<<<SCAN_NB, 1024>>>();
    k_scan2<<<1, 128>>>();
    k_scan3<<<(N_NODES + 255) / 256, 256>>>();
    k_fill <<<(N_EDGES + 255) / 256, 256>>>(ei);

    k_agg1 <<<(N_NODES * 32 + 255) / 256, 256>>>();

    dim3 g1(M_PAD / 128, D_HID / 64);
    k_hmma1<<<g1, 256>>>(W1, b1);

    dim3 g2(M_PAD / 128, D_OUT / 64);
    k_hmma2<<<g2, 256>>>(W2);

    k_out  <<<(N_NODES * 32 + 255) / 256, 256>>>(b2, out);
}

// round 14
// speedup vs baseline: 1.2676x; 1.0009x over previous
#include <cuda_runtime.h>
#include <cuda_bf16.h>
#include <math.h>

#define N_NODES 100000
#define M_PAD   100096              // 782 * 128
#define D_IN    128
#define D_HID   256
#define D_OUT   64
#define N_EDGES 1600000
#define SCAN_NB ((N_NODES + 1023) / 1024)   // 98

typedef unsigned int       u32;
typedef unsigned long long u64;
typedef __nv_bfloat16      bf16;
typedef __nv_bfloat162     bf162;

// ---------------- scratch (static device globals; no allocation) ----------------
__device__ int   g_is64;
__device__ int   g_cnt[N_NODES];
__device__ int   g_cur[N_NODES];
__device__ int   g_off[N_NODES + 1];
__device__ int   g_bsum[128];
__device__ int   g_csr[N_EDGES];
__device__ bf16  g_xb[(size_t)N_NODES * D_IN];    // bf16 copy of x
__device__ bf16  g_a1b[(size_t)M_PAD * D_IN];     // agg1 result, bf16 (padded rows stay 0)
__device__ bf16  g_hb[(size_t)M_PAD * D_HID];     // layer-1 output, bf16
__device__ bf16  g_zb[(size_t)M_PAD * D_OUT];     // layer-2 pre-agg logits, bf16

// ---------------- helpers ----------------
__device__ __forceinline__ u32 smem_u32(const void* p) {
    u32 a;
    asm("{ .reg .u64 t; cvta.to.shared.u64 t, %1; cvt.u32.u64 %0, t; }" : "=r"(a) : "l"(p));
    return a;
}
__device__ __forceinline__ void ldsm4(u32* r, u32 addr) {
    asm volatile("ldmatrix.sync.aligned.m8n8.x4.shared.b16 {%0,%1,%2,%3}, [%4];"
        : "=r"(r[0]), "=r"(r[1]), "=r"(r[2]), "=r"(r[3]) : "r"(addr));
}
__device__ __forceinline__ void mma16816(float* c, const u32* a, u32 b0, u32 b1) {
    asm volatile(
        "mma.sync.aligned.m16n8k16.row.col.f32.bf16.bf16.f32 "
        "{%0,%1,%2,%3}, {%4,%5,%6,%7}, {%8,%9}, {%0,%1,%2,%3};"
        : "+f"(c[0]), "+f"(c[1]), "+f"(c[2]), "+f"(c[3])
        : "r"(a[0]), "r"(a[1]), "r"(a[2]), "r"(a[3]), "r"(b0), "r"(b1));
}

// edge index accessors (dtype decided at runtime)
__device__ __forceinline__ int edge_src(const void* ei, int i, int is64) {
    return is64 ? (int)((const long long*)ei)[i] : ((const int*)ei)[i];
}
__device__ __forceinline__ int edge_dst(const void* ei, int i, int is64) {
    return is64 ? (int)((const long long*)ei)[N_EDGES + i] : ((const int*)ei)[N_EDGES + i];
}

__global__ void k_detect(const int* __restrict__ ei_words) {
    int all_zero = 1;
    for (int i = 0; i < 64; i++)
        if (ei_words[2 * i + 1] != 0) { all_zero = 0; break; }
    g_is64 = all_zero;
}

// ---------------- CSR build ----------------
__global__ void k_zero() {
    int i = blockIdx.x * blockDim.x + threadIdx.x;
    if (i < N_NODES) { g_cnt[i] = 0; g_cur[i] = 0; }
}

__global__ void k_hist(const void* __restrict__ ei) {
    int is64 = g_is64;
    int i = blockIdx.x * blockDim.x + threadIdx.x;
    if (i < N_EDGES) {
        int d = edge_dst(ei, i, is64);
        if (d >= 0 && d < N_NODES) atomicAdd(&g_cnt[d], 1);
    }
}

__device__ __forceinline__ int warp_incl_scan(int x, int lane) {
#pragma unroll
    for (int o = 1; o < 32; o <<= 1) {
        int t = __shfl_up_sync(0xffffffffu, x, o);
        if (lane >= o) x += t;
    }
    return x;
}

__global__ void k_scan1() {
    int b = blockIdx.x, tid = threadIdx.x;
    int i = b * 1024 + tid;
    int v = (i < N_NODES) ? g_cnt[i] : 0;
    int lane = tid & 31, w = tid >> 5;
    int x = warp_incl_scan(v, lane);
    __shared__ int ws[32];
    if (lane == 31) ws[w] = x;
    __syncthreads();
    if (w == 0) {
        int t = ws[lane];
        t = warp_incl_scan(t, lane);
        ws[lane] = t;
    }
    __syncthreads();
    int incl = x + (w ? ws[w - 1] : 0);
    if (i < N_NODES) g_off[i] = incl - v;
    if (tid == 1023) g_bsum[b] = incl;
}

__global__ void k_scan2() {
    int tid = threadIdx.x, lane = tid & 31, w = tid >> 5;
    int v = (tid < SCAN_NB) ? g_bsum[tid] : 0;
    int x = warp_incl_scan(v, lane);
    __shared__ int ws[4];
    if (lane == 31) ws[w] = x;
    __syncthreads();
    int add = 0;
#pragma unroll
    for (int i = 0; i < 4; i++) if (i < w) add += ws[i];
    int incl = x + add;
    if (tid < SCAN_NB) g_bsum[tid] = incl - v;
}

__global__ void k_scan3() {
    int i = blockIdx.x * blockDim.x + threadIdx.x;
    if (i < N_NODES) g_off[i] += g_bsum[i >> 10];
    if (i == 0) g_off[N_NODES] = N_EDGES;
}

__global__ void k_fill(const void* __restrict__ ei) {
    int is64 = g_is64;
    int i = blockIdx.x * blockDim.x + threadIdx.x;
    if (i < N_EDGES) {
        int d = edge_dst(ei, i, is64);
        int s = edge_src(ei, i, is64);
        if (d >= 0 && d < N_NODES && s >= 0 && s < N_NODES) {
            int p = atomicAdd(&g_cur[d], 1);
            g_csr[g_off[d] + p] = s;
        }
    }
}

// ---------------- x -> bf16 conversion ----------------
__global__ void k_xcvt(const float* __restrict__ x) {
    int i = blockIdx.x * blockDim.x + threadIdx.x;   // one float4 per thread
    if (i < N_NODES * D_IN / 4) {
        float4 v = ((const float4*)x)[i];
        *(bf162*)(g_xb + (size_t)i * 4)     = bf162(__float2bfloat16_rn(v.x), __float2bfloat16_rn(v.y));
        *(bf162*)(g_xb + (size_t)i * 4 + 2) = bf162(__float2bfloat16_rn(v.z), __float2bfloat16_rn(v.w));
    }
}

// ---------------- aggregation 1: mean over in-neighbors of bf16 x, bf16 out ----------------
__global__ void k_agg1() {
    int warp = (blockIdx.x * blockDim.x + threadIdx.x) >> 5;
    if (warp >= N_NODES) return;
    int lane = threadIdx.x & 31;
    int s0 = g_off[warp], s1 = g_off[warp + 1];
    float4 acc = make_float4(0.f, 0.f, 0.f, 0.f);
    int e = s0;
    for (; e + 2 <= s1; e += 2) {            // 2-way unroll for MLP
        int sa = g_csr[e], sb = g_csr[e + 1];
        const bf162* pa = (const bf162*)(g_xb + (size_t)sa * D_IN + lane * 4);
        const bf162* pb = (const bf162*)(g_xb + (size_t)sb * D_IN + lane * 4);
        bf162 a0 = pa[0], a1 = pa[1], b0 = pb[0], b1 = pb[1];
        float2 f;
        f = __bfloat1622float2(a0); acc.x += f.x; acc.y += f.y;
        f = __bfloat1622float2(a1); acc.z += f.x; acc.w += f.y;
        f = __bfloat1622float2(b0); acc.x += f.x; acc.y += f.y;
        f = __bfloat1622float2(b1); acc.z += f.x; acc.w += f.y;
    }
    if (e < s1) {
        int s = g_csr[e];
        const bf162* p = (const bf162*)(g_xb + (size_t)s * D_IN + lane * 4);
        float2 f0 = __bfloat1622float2(p[0]);
        float2 f1 = __bfloat1622float2(p[1]);
        acc.x += f0.x; acc.y += f0.y; acc.z += f1.x; acc.w += f1.y;
    }
    float sc = 1.f / (float)max(s1 - s0, 1);
    bf162 o0(__float2bfloat16_rn(acc.x * sc), __float2bfloat16_rn(acc.y * sc));
    bf162 o1(__float2bfloat16_rn(acc.z * sc), __float2bfloat16_rn(acc.w * sc));
    bf162* q = (bf162*)(g_a1b + (size_t)warp * D_IN + lane * 4);
    q[0] = o0; q[1] = o1;
}

// ================= plain bf16 tensor-core GEMM =================
// C[M_PAD, LDC] = A[M_PAD, KTOT](bf16) @ B[*, KTOT](fp32->bf16)^T (+bias, relu), bf16 out.
// Tiles BM=128 BN=64 BK=32; 256 threads = 8 warps (4 m x 2 n). Single-buffered smem.
// B tiles stored n-major/k-contiguous == native col-major fragment -> NON-trans ldmatrix.
#define AST 40     // bf16 elems per A/B smem row (80 B, 16B-aligned rows)

template <int KTOT, int LDC, bool RELU, bool HASBIAS>
__device__ __forceinline__ void hmma_body(const bf16* __restrict__ A,
                                          const float* __restrict__ B,
                                          const float* __restrict__ bias,
                                          bf16* __restrict__ C) {
    __shared__ __align__(16) bf16 sA[128 * AST];
    __shared__ __align__(16) bf16 sB[64 * AST];

    const int tid  = threadIdx.x;
    const int wid  = tid >> 5;
    const int lane = tid & 31;
    const int g    = lane >> 2;
    const int tig  = lane & 3;
    const int m0   = blockIdx.x * 128;
    const int n0   = blockIdx.y * 64;
    const int wm   = (wid & 3) * 32;
    const int wn   = (wid >> 2) * 32;

    const u32 uA = smem_u32(sA);
    const u32 uB = smem_u32(sB);
    const int lr = lane & 15;
    const int lc = (lane >> 4) << 3;

    float acc[2][4][4];
#pragma unroll
    for (int i = 0; i < 2; i++)
#pragma unroll
        for (int j = 0; j < 4; j++)
#pragma unroll
            for (int c = 0; c < 4; c++) acc[i][j][c] = 0.f;

    for (int kt = 0; kt < KTOT / 32; kt++) {
        const int k0 = kt * 32;
        __syncthreads();
        // ---- stage A: 128 x 32 bf16 raw copy (16B per thread, 2 iters) ----
#pragma unroll
        for (int i = 0; i < 2; i++) {
            int e = tid + i * 256;              // 0..511
            int row = e >> 2, c8 = (e & 3) * 8;
            *(uint4*)(sA + row * AST + c8) =
                *(const uint4*)(A + (size_t)(m0 + row) * KTOT + k0 + c8);
        }
        // ---- stage B: 64 x 32 fp32 -> bf16 (rn) ----
#pragma unroll
        for (int i = 0; i < 2; i++) {
            int e = tid + i * 256;              // 0..511
            int row = e >> 3, c4 = (e & 7) * 4;
            float4 v = *(const float4*)(B + (size_t)(n0 + row) * KTOT + k0 + c4);
            int o = row * AST + c4;
            *(bf162*)(sB + o)     = bf162(__float2bfloat16_rn(v.x), __float2bfloat16_rn(v.y));
            *(bf162*)(sB + o + 2) = bf162(__float2bfloat16_rn(v.z), __float2bfloat16_rn(v.w));
        }
        __syncthreads();

        // ---- compute: 2 k-slabs of 16 ----
#pragma unroll
        for (int ks = 0; ks < 2; ks++) {
            const int kc = ks * 16 + lc;
            u32 ah[2][4], bh[2][4];
#pragma unroll
            for (int ma = 0; ma < 2; ma++) {
                u32 off = (u32)((wm + ma * 16 + lr) * AST + kc) * 2;
                ldsm4(ah[ma], uA + off);
            }
#pragma unroll
            for (int p = 0; p < 2; p++) {
                u32 off = (u32)((wn + p * 16 + lr) * AST + kc) * 2;
                ldsm4(bh[p], uB + off);
            }
#pragma unroll
            for (int ma = 0; ma < 2; ma++)
#pragma unroll
                for (int nb = 0; nb < 4; nb++) {
                    int p = nb >> 1, j = nb & 1;
                    mma16816(acc[ma][nb], ah[ma], bh[p][j], bh[p][j + 2]);
                }
        }
    }

    // ---- epilogue: bf16 out ----
#pragma unroll
    for (int ma = 0; ma < 2; ma++)
#pragma unroll
        for (int nb = 0; nb < 4; nb++) {
            int row = m0 + wm + ma * 16 + g;
            int col = n0 + wn + nb * 8 + 2 * tig;
            float c0 = acc[ma][nb][0], c1 = acc[ma][nb][1];
            float c2 = acc[ma][nb][2], c3 = acc[ma][nb][3];
            if (HASBIAS) {
                float bv0 = __ldg(bias + col), bv1 = __ldg(bias + col + 1);
                c0 += bv0; c1 += bv1; c2 += bv0; c3 += bv1;
            }
            if (RELU) {
                c0 = fmaxf(c0, 0.f); c1 = fmaxf(c1, 0.f);
                c2 = fmaxf(c2, 0.f); c3 = fmaxf(c3, 0.f);
            }
            *(bf162*)(C + (size_t)row * LDC + col) =
                bf162(__float2bfloat16_rn(c0), __float2bfloat16_rn(c1));
            *(bf162*)(C + (size_t)(row + 8) * LDC + col) =
                bf162(__float2bfloat16_rn(c2), __float2bfloat16_rn(c3));
        }
}

__global__ void __launch_bounds__(256) k_hmma1(const float* __restrict__ W1,
                                               const float* __restrict__ b1) {
    hmma_body<D_IN, D_HID, true, true>(g_a1b, W1, b1, g_hb);
}
__global__ void __launch_bounds__(256) k_hmma2(const float* __restrict__ W2) {
    hmma_body<D_HID, D_OUT, false, false>(g_hb, W2, nullptr, g_zb);
}

// ---------------- final: agg2 (bf16 z) + bias + log_softmax ----------------
__global__ void k_out(const float* __restrict__ b2, float* __restrict__ out) {
    int warp = (blockIdx.x * blockDim.x + threadIdx.x) >> 5;
    if (warp >= N_NODES) return;
    int lane = threadIdx.x & 31;
    int s0 = g_off[warp], s1 = g_off[warp + 1];
    float2 acc = make_float2(0.f, 0.f);
    int e = s0;
    for (; e + 2 <= s1; e += 2) {            // 2-way unroll for MLP
        int sa = g_csr[e], sb = g_csr[e + 1];
        bf162 va = *(const bf162*)(g_zb + (size_t)sa * D_OUT + lane * 2);
        bf162 vb = *(const bf162*)(g_zb + (size_t)sb * D_OUT + lane * 2);
        float2 fa = __bfloat1622float2(va);
        float2 fb = __bfloat1622float2(vb);
        acc.x += fa.x + fb.x; acc.y += fa.y + fb.y;
    }
    if (e < s1) {
        int s = g_csr[e];
        float2 f = __bfloat1622float2(*(const bf162*)(g_zb + (size_t)s * D_OUT + lane * 2));
        acc.x += f.x; acc.y += f.y;
    }
    float sc = 1.f / (float)max(s1 - s0, 1);
    float y0 = acc.x * sc + b2[lane * 2];
    float y1 = acc.y * sc + b2[lane * 2 + 1];
    float m = fmaxf(y0, y1);
#pragma unroll
    for (int o = 16; o; o >>= 1) m = fmaxf(m, __shfl_xor_sync(0xffffffffu, m, o));
    float se = expf(y0 - m) + expf(y1 - m);
#pragma unroll
    for (int o = 16; o; o >>= 1) se += __shfl_xor_sync(0xffffffffu, se, o);
    float lse = m + logf(se);
    float2 r = make_float2(y0 - lse, y1 - lse);
    *(float2*)(out + (size_t)warp * D_OUT + lane * 2) = r;
}

// ---------------- launch ----------------
extern "C" void kernel_launch(void* const* d_in, const int* in_sizes, int n_in,
                              void* d_out, int out_size) {
    const float* x  = (const float*)d_in[0];
    const void*  ei = d_in[1];
    const float* W1 = (const float*)d_in[2];
    const float* b1 = (const float*)d_in[3];
    const float* W2 = (const float*)d_in[4];
    const float* b2 = (const float*)d_in[5];
    float* out = (float*)d_out;

    k_detect<<<1, 1>>>((const int*)ei);
    k_zero <<<(N_NODES + 255) / 256, 256>>>();
    k_hist <<<(N_EDGES + 255) / 256, 256>>>(ei);
    k_xcvt <<<(N_NODES * D_IN / 4 + 255) / 256, 256>>>(x);
    k_scan1<<<SCAN_NB, 1024>>>();
    k_scan2<<<1, 128>>>();
    k_scan3<<<(N_NODES + 255) / 256, 256>>>();
    k_fill <<<(N_EDGES + 255) / 256, 256>>>(ei);

    k_agg1 <<<(N_NODES * 32 + 255) / 256, 256>>>();

    dim3 g1(M_PAD / 128, D_HID / 64);
    k_hmma1<<<g1, 256>>>(W1, b1);

    dim3 g2(M_PAD / 128, D_OUT / 64);
    k_hmma2<<<g2, 256>>>(W2);

    k_out  <<<(N_NODES * 32 + 255) / 256, 256>>>(b2, out);
}